// round 15
// baseline (speedup 1.0000x reference)
#include <cuda_runtime.h>
#include <cuda_bf16.h>

#define WIDTH 4096
#define HALFW 2048
#define DEPTH 32
#define BATCH 16384

typedef unsigned long long ull;

// ---- group bit-mappings (single source of truth for prologue + main) ----
// WMAP chosen to maximize warp-local transposes: W0=W1={8,9} (s=5 local),
// W2=W3={10,11} (s=15 local), W5=W6={10,11} (s=30 local). G7 = LOAD mapping,
// derived from rotl4-coalescing (NOT free — see R14 post-mortem).
__device__ constexpr int LMAP[8][5] = {
    {0,1,2,10,11}, // G0  (stages 0-4,   d=7,6,5,4,3)
    {3,4,5,6,7},   // G1  (stages 5-9,   d=2,1,0,11,10)
    {0,1,2,3,4},   // G2  (stages 10-14, d=9,8,7,6,5)
    {5,6,7,8,9},   // G3  (stages 15-19, d=4,3,2,1,0)
    {2,3,4,5,6},   // G4  (stages 20-24, d=11,10,9,8,7)
    {0,1,7,8,9},   // G5  (stages 25-29, d=6,5,4,3,2)
    {2,3,4,5,6},   // G6  (stages 30-31, d=1,0) -> coalesced store
    {10,11,0,1,2}  // G7 = LOAD
};
__device__ constexpr int RMAP[8][5] = {
    {3,4,5,6,7},
    {0,1,2,10,11},
    {5,6,7,8,9},
    {0,1,2,3,4},
    {7,8,9,10,11},
    {2,3,4,5,6},
    {0,1,7,8,9},
    {5,6,7,8,9}
};
__device__ constexpr int WMAP[8][2] = {
    {8,9},{8,9},{10,11},{10,11},{0,1},{10,11},{10,11},{3,4}
};
__device__ constexpr int CP[DEPTH] = {4,3,2,1,0, 2,1,0,4,3, 4,3,2,1,0, 4,3,2,1,0,
                                      4,3,2,1,0, 4,3,2,1,0, 1,0};
__device__ constexpr int CG[DEPTH] = {0,0,0,0,0,1,1,1,1,1,2,2,2,2,2,3,3,3,3,3,
                                      4,4,4,4,4,5,5,5,5,5,6,6};

// GF(2)-linear smem swizzle. Address bits 0..4 = j[0..4] ^ j[5..9] ^ (j[10,11]<<3):
// bijective in the 5 lane bits for every group's lane pattern (verified per group),
// and address bits 5..11 = j bits 5..11 (warp regions disjoint for warp-local use).
__device__ constexpr int csig(int j) {
    return j ^ ((j >> 5) & 31) ^ (((j >> 10) & 3) << 3);
}
__device__ constexpr int scat5(int v, const int* m) {
    return ((v & 1) << m[0]) | (((v >> 1) & 1) << m[1]) | (((v >> 2) & 1) << m[2])
         | (((v >> 3) & 1) << m[3]) | (((v >> 4) & 1) << m[4]);
}

// Per-stage coefficient tables, pre-permuted into per-warp slot order.
// Entry [s][(w<<8)|(h<<5)|lane] = float4(c0, s0, c1, s1) for rc=2h, 2h+1.
__device__ float4 g_tab4[DEPTH][1024];

__global__ void ob_tables(const float* __restrict__ P) {
    int idx = blockIdx.x * blockDim.x + threadIdx.x;
    if (idx >= DEPTH * 1024) return;
    int s = idx >> 10, v = idx & 1023;
    int g = CG[s], p = CP[s], sm = (s + 4) % 12;
    int lane = v & 31, h = (v >> 5) & 7, w = v >> 8;
    float out[4];
    for (int i = 0; i < 2; ++i) {
        int rc = 2 * h + i;
        int r0 = ((rc >> p) << (p + 1)) | (rc & ((1 << p) - 1));   // insert 0 at bit p
        int j = 0;
        for (int t = 0; t < 5; ++t) j |= ((lane >> t) & 1) << LMAP[g][t];
        for (int t = 0; t < 5; ++t) j |= ((r0 >> t) & 1) << RMAP[g][t];
        for (int t = 0; t < 2; ++t) j |= ((w >> t) & 1) << WMAP[g][t];
        int k = (((j << sm) | (j >> (12 - sm))) & 0xFFF) & 0x7FF;  // angle index
        float th = P[k * DEPTH + s];                               // params (HALF, DEPTH)
        out[2 * i] = cosf(th);
        out[2 * i + 1] = sinf(th);
    }
    g_tab4[s][v] = make_float4(out[0], out[1], out[2], out[3]);
}

// ---- packed f32x2 helpers (sm_103a) ----
__device__ __forceinline__ ull f2mul(ull a, ull b) {
    ull d; asm("mul.rn.f32x2 %0, %1, %2;" : "=l"(d) : "l"(a), "l"(b)); return d;
}
__device__ __forceinline__ ull f2fma(ull a, ull b, ull c) {
    ull d; asm("fma.rn.f32x2 %0, %1, %2, %3;" : "=l"(d) : "l"(a), "l"(b), "l"(c)); return d;
}
__device__ __forceinline__ ull fpack(float lo, float hi) {
    ull d; asm("mov.b64 %0, {%1, %2};" : "=l"(d) : "f"(lo), "f"(hi)); return d;
}
__device__ __forceinline__ void funpack(float& lo, float& hi, ull v) {
    asm("mov.b64 {%0, %1}, %2;" : "=f"(lo), "=f"(hi) : "l"(v));
}

// transpose 4-row packed state from group GF to GT via S.
// CTAW=true: w-bits move -> CTA-wide barriers. CTAW=false: w-bits identical in
// GF and GT -> each warp's region of S is private -> __syncwarp suffices.
template<int GF, int GT, bool CTAW>
__device__ __forceinline__ void xpose(ull* a01, ull* a23, ull* S, int lane, int w) {
    int lwo = 0, lwn = 0;
    #pragma unroll
    for (int t = 0; t < 5; ++t) {
        lwo |= ((lane >> t) & 1) << LMAP[GF][t];
        lwn |= ((lane >> t) & 1) << LMAP[GT][t];
    }
    #pragma unroll
    for (int t = 0; t < 2; ++t) {
        lwo |= ((w >> t) & 1) << WMAP[GF][t];
        lwn |= ((w >> t) & 1) << WMAP[GT][t];
    }
    const int so = csig(lwo), sn = csig(lwn);
    if (CTAW) __syncthreads(); else __syncwarp();
    #pragma unroll
    for (int r = 0; r < 32; ++r) S[so ^ csig(scat5(r, RMAP[GF]))] = a01[r];
    if (CTAW) __syncthreads(); else __syncwarp();
    #pragma unroll
    for (int r = 0; r < 32; ++r) a01[r] = S[sn ^ csig(scat5(r, RMAP[GT]))];
    if (CTAW) __syncthreads(); else __syncwarp();
    #pragma unroll
    for (int r = 0; r < 32; ++r) S[so ^ csig(scat5(r, RMAP[GF]))] = a23[r];
    if (CTAW) __syncthreads(); else __syncwarp();
    #pragma unroll
    for (int r = 0; r < 32; ++r) a23[r] = S[sn ^ csig(scat5(r, RMAP[GT]))];
}

template<int P>
__device__ __forceinline__ void stage_body(ull* a01, ull* a23,
                                           const float4* __restrict__ Tw, int lane) {
    #pragma unroll
    for (int h = 0; h < 8; ++h) {
        float4 q = Tw[(h << 5) | lane];    // conflict-free LDS.128: rc=2h, 2h+1
        #pragma unroll
        for (int i = 0; i < 2; ++i) {
            const int rc = 2 * h + i;
            const int r0 = ((rc >> P) << (P + 1)) | (rc & ((1 << P) - 1));
            const int r1 = r0 | (1 << P);
            const float c  = i ? q.z : q.x;
            const float sv = i ? q.w : q.y;
            ull cc  = fpack(c, c);
            ull ss  = fpack(sv, sv);
            ull nss = ss ^ 0x8000000080000000ULL;
            ull A0 = a01[r0], B0 = a01[r1];
            ull A1 = a23[r0], B1 = a23[r1];
            a01[r0] = f2fma(cc, A0, f2mul(ss,  B0));
            a01[r1] = f2fma(cc, B0, f2mul(nss, A0));
            a23[r0] = f2fma(cc, A1, f2mul(ss,  B1));
            a23[r1] = f2fma(cc, B1, f2mul(nss, A1));
        }
    }
}

__global__ __launch_bounds__(128, 3)
void ob_main(const float* __restrict__ X, float* __restrict__ O) {
    extern __shared__ char smem[];
    // per-warp double-buffered coefficient slices: [buf][warp][256] float4 = 32 KB
    float4 (*wtab)[4][256] = (float4(*)[4][256])smem;
    ull* S = (ull*)(smem + 2 * 4 * 256 * sizeof(float4));   // 32 KB transpose buf

    const int tid  = threadIdx.x;        // 128 threads = one 4-row group
    const int lane = tid & 31;
    const int w    = tid >> 5;
    const long r0base = (long)blockIdx.x * 4;

    ull a01[32], a23[32];   // packed rows (0,1) and (2,3); reg idx = 5 RMAP bits

    // ---- prefetch this warp's stage-0 slice (4 KB; 8 x 16B per lane) ----
    {
        const float4* src = &g_tab4[0][w << 8];
        #pragma unroll
        for (int c = 0; c < 8; ++c) {
            int e = c * 32 + lane;
            unsigned dst = (unsigned)__cvta_generic_to_shared(&wtab[0][w][e]);
            asm volatile("cp.async.ca.shared.global [%0], [%1], 16;" :: "r"(dst), "l"(src + e));
        }
        asm volatile("cp.async.commit_group;");
    }

    // ---- coalesced load under LOAD mapping (G7, rotl4-derived): r = m + 8*comp ----
    {
        const float4* s0 = (const float4*)(X + r0base * WIDTH);
        const float4* s1 = (const float4*)(X + (r0base + 1) * WIDTH);
        const float4* s2 = (const float4*)(X + (r0base + 2) * WIDTH);
        const float4* s3 = (const float4*)(X + (r0base + 3) * WIDTH);
        #pragma unroll
        for (int m = 0; m < 8; ++m) {
            int a4 = (m << 7) | (w << 5) | lane;
            float4 v0 = s0[a4], v1 = s1[a4], v2 = s2[a4], v3 = s3[a4];
            a01[m]      = fpack(v0.x, v1.x);  a23[m]      = fpack(v2.x, v3.x);
            a01[8 + m]  = fpack(v0.y, v1.y);  a23[8 + m]  = fpack(v2.y, v3.y);
            a01[16 + m] = fpack(v0.z, v1.z);  a23[16 + m] = fpack(v2.z, v3.z);
            a01[24 + m] = fpack(v0.w, v1.w);  a23[24 + m] = fpack(v2.w, v3.w);
        }
    }

    xpose<7, 0, true>(a01, a23, S, lane, w);   // LOAD -> G0 (w moves: CTA-wide)

    // ---- 32 stages; per-warp tables, cp.async issued before transpose ----
    #pragma unroll 1
    for (int s = 0; s < DEPTH; ++s) {
        if (s + 1 < DEPTH) {   // issue next stage's slice first: max flight time
            const float4* src = &g_tab4[s + 1][w << 8];
            float4* dstbuf = &wtab[(s + 1) & 1][w][0];
            #pragma unroll
            for (int c = 0; c < 8; ++c) {
                int e = c * 32 + lane;
                unsigned dst = (unsigned)__cvta_generic_to_shared(dstbuf + e);
                asm volatile("cp.async.ca.shared.global [%0], [%1], 16;" :: "r"(dst), "l"(src + e));
            }
            asm volatile("cp.async.commit_group;");
        }
        switch (s) {           // group-boundary transposes (cp.async flies under)
            case 5:  xpose<0, 1, false>(a01, a23, S, lane, w); break;  // W {8,9}=={8,9}
            case 10: xpose<1, 2, true >(a01, a23, S, lane, w); break;  // w moves
            case 15: xpose<2, 3, false>(a01, a23, S, lane, w); break;  // W {10,11}
            case 20: xpose<3, 4, true >(a01, a23, S, lane, w); break;  // w moves
            case 25: xpose<4, 5, true >(a01, a23, S, lane, w); break;  // w moves
            case 30: xpose<5, 6, false>(a01, a23, S, lane, w); break;  // W {10,11}
            default: break;
        }
        if (s + 1 < DEPTH) asm volatile("cp.async.wait_group 1;");  // stage-s landed
        else               asm volatile("cp.async.wait_group 0;");
        __syncwarp();          // all lanes' chunks visible

        const float4* __restrict__ Tw = wtab[s & 1][w];
        switch (CP[s]) {
            case 0: stage_body<0>(a01, a23, Tw, lane); break;
            case 1: stage_body<1>(a01, a23, Tw, lane); break;
            case 2: stage_body<2>(a01, a23, Tw, lane); break;
            case 3: stage_body<3>(a01, a23, Tw, lane); break;
            default: stage_body<4>(a01, a23, Tw, lane); break;
        }
    }

    // ---- store under G6 mapping: out[j]=b32[j], float4-coalesced ----
    {
        float4* o0 = (float4*)(O + r0base * WIDTH);
        float4* o1 = (float4*)(O + (r0base + 1) * WIDTH);
        float4* o2 = (float4*)(O + (r0base + 2) * WIDTH);
        float4* o3 = (float4*)(O + (r0base + 3) * WIDTH);
        #pragma unroll
        for (int e = 0; e < 8; ++e) {
            int j4 = (w << 8) | (e << 5) | lane;
            float p0[4], p1[4], p2[4], p3[4];
            #pragma unroll
            for (int q = 0; q < 4; ++q) {
                funpack(p0[q], p1[q], a01[e * 4 + q]);
                funpack(p2[q], p3[q], a23[e * 4 + q]);
            }
            o0[j4] = make_float4(p0[0], p0[1], p0[2], p0[3]);
            o1[j4] = make_float4(p1[0], p1[1], p1[2], p1[3]);
            o2[j4] = make_float4(p2[0], p2[1], p2[2], p2[3]);
            o3[j4] = make_float4(p3[0], p3[1], p3[2], p3[3]);
        }
    }
}

extern "C" void kernel_launch(void* const* d_in, const int* in_sizes, int n_in,
                              void* d_out, int out_size) {
    const float* X = (const float*)d_in[0];
    const float* P = (const float*)d_in[1];
    if (n_in >= 2 && in_sizes[0] == DEPTH * HALFW) { const float* tmp = X; X = P; P = tmp; }
    float* O = (float*)d_out;
    const int smem = 2 * 4 * 256 * sizeof(float4) + WIDTH * sizeof(ull);  // 64 KB
    cudaFuncSetAttribute(ob_main, cudaFuncAttributeMaxDynamicSharedMemorySize, smem);
    ob_tables<<<(DEPTH * 1024 + 255) / 256, 256>>>(P);
    ob_main<<<BATCH / 4, 128, smem>>>(X, O);
}

// round 16
// speedup vs baseline: 1.1061x; 1.1061x over previous
#include <cuda_runtime.h>
#include <cuda_bf16.h>

#define WIDTH 4096
#define HALFW 2048
#define DEPTH 32
#define BATCH 16384

typedef unsigned long long ull;

// ---- group bit-mappings (single source of truth for prologue + main) ----
// (R13 maps, verified at 468 us.)
__device__ constexpr int LMAP[8][5] = {
    {0,1,2,8,9},   // G0  (stages 0-4,   d=7,6,5,4,3)
    {5,6,7,8,9},   // G1  (stages 5-9,   d=2,1,0,11,10)
    {0,1,2,3,4},   // G2  (stages 10-14, d=9,8,7,6,5)
    {5,6,7,8,9},   // G3  (stages 15-19, d=4,3,2,1,0)
    {0,1,2,3,4},   // G4  (stages 20-24, d=11,10,9,8,7)
    {0,1,7,8,9},   // G5  (stages 25-29, d=6,5,4,3,2)
    {2,3,4,5,6},   // G6  (stages 30-31, d=1,0) -> coalesced store
    {10,11,0,1,2}  // G7 = LOAD (rotl4-derived; not a free choice)
};
__device__ constexpr int RMAP[8][5] = {
    {3,4,5,6,7},
    {0,1,2,10,11},
    {5,6,7,8,9},
    {0,1,2,3,4},
    {7,8,9,10,11},
    {2,3,4,5,6},
    {0,1,7,8,9},
    {5,6,7,8,9}
};
__device__ constexpr int WMAP[8][2] = {
    {10,11},{3,4},{10,11},{10,11},{5,6},{10,11},{10,11},{3,4}
};
__device__ constexpr int CP[DEPTH] = {4,3,2,1,0, 2,1,0,4,3, 4,3,2,1,0, 4,3,2,1,0,
                                      4,3,2,1,0, 4,3,2,1,0, 1,0};
__device__ constexpr int CG[DEPTH] = {0,0,0,0,0,1,1,1,1,1,2,2,2,2,2,3,3,3,3,3,
                                      4,4,4,4,4,5,5,5,5,5,6,6};

// GF(2)-linear smem swizzle (conflict-free for all R13 group patterns).
__device__ constexpr int csig(int j) {
    return j ^ ((j >> 5) & 31) ^ (((j >> 10) & 3) << 3);
}
__device__ constexpr int scat5(int v, const int* m) {
    return ((v & 1) << m[0]) | (((v >> 1) & 1) << m[1]) | (((v >> 2) & 1) << m[2])
         | (((v >> 3) & 1) << m[3]) | (((v >> 4) & 1) << m[4]);
}

// Per-stage coefficient tables, pre-permuted into per-warp slot order.
// Entry [s][(w<<8)|(h<<5)|lane] = float4(c0, s0, c1, s1) for rc=2h, 2h+1.
__device__ float4 g_tab4[DEPTH][1024];

__global__ void ob_tables(const float* __restrict__ P) {
    int idx = blockIdx.x * blockDim.x + threadIdx.x;
    if (idx >= DEPTH * 1024) return;
    int s = idx >> 10, v = idx & 1023;
    int g = CG[s], p = CP[s], sm = (s + 4) % 12;
    int lane = v & 31, h = (v >> 5) & 7, w = v >> 8;
    float out[4];
    for (int i = 0; i < 2; ++i) {
        int rc = 2 * h + i;
        int r0 = ((rc >> p) << (p + 1)) | (rc & ((1 << p) - 1));   // insert 0 at bit p
        int j = 0;
        for (int t = 0; t < 5; ++t) j |= ((lane >> t) & 1) << LMAP[g][t];
        for (int t = 0; t < 5; ++t) j |= ((r0 >> t) & 1) << RMAP[g][t];
        for (int t = 0; t < 2; ++t) j |= ((w >> t) & 1) << WMAP[g][t];
        int k = (((j << sm) | (j >> (12 - sm))) & 0xFFF) & 0x7FF;  // angle index
        float th = P[k * DEPTH + s];                               // params (HALF, DEPTH)
        out[2 * i] = cosf(th);
        out[2 * i + 1] = sinf(th);
    }
    g_tab4[s][v] = make_float4(out[0], out[1], out[2], out[3]);
}

// ---- packed f32x2 helpers (sm_103a) ----
__device__ __forceinline__ ull f2mul(ull a, ull b) {
    ull d; asm("mul.rn.f32x2 %0, %1, %2;" : "=l"(d) : "l"(a), "l"(b)); return d;
}
__device__ __forceinline__ ull f2fma(ull a, ull b, ull c) {
    ull d; asm("fma.rn.f32x2 %0, %1, %2, %3;" : "=l"(d) : "l"(a), "l"(b), "l"(c)); return d;
}
__device__ __forceinline__ ull fpack(float lo, float hi) {
    ull d; asm("mov.b64 %0, {%1, %2};" : "=l"(d) : "f"(lo), "f"(hi)); return d;
}
__device__ __forceinline__ void funpack(float& lo, float& hi, ull v) {
    asm("mov.b64 {%0, %1}, %2;" : "=f"(lo), "=f"(hi) : "l"(v));
}

// transpose 4-row packed state from group GF to GT via S.
// CTAW=true: w-bits move -> CTA-wide barriers. CTAW=false: w-bits identical in
// GF and GT (addr bits 10,11 = w -> private warp regions) -> __syncwarp.
template<int GF, int GT, bool CTAW>
__device__ __forceinline__ void xpose(ull* a01, ull* a23, ull* S, int lane, int w) {
    int lwo = 0, lwn = 0;
    #pragma unroll
    for (int t = 0; t < 5; ++t) {
        lwo |= ((lane >> t) & 1) << LMAP[GF][t];
        lwn |= ((lane >> t) & 1) << LMAP[GT][t];
    }
    #pragma unroll
    for (int t = 0; t < 2; ++t) {
        lwo |= ((w >> t) & 1) << WMAP[GF][t];
        lwn |= ((w >> t) & 1) << WMAP[GT][t];
    }
    const int so = csig(lwo), sn = csig(lwn);
    if (CTAW) __syncthreads(); else __syncwarp();
    #pragma unroll
    for (int r = 0; r < 32; ++r) S[so ^ csig(scat5(r, RMAP[GF]))] = a01[r];
    if (CTAW) __syncthreads(); else __syncwarp();
    #pragma unroll
    for (int r = 0; r < 32; ++r) a01[r] = S[sn ^ csig(scat5(r, RMAP[GT]))];
    if (CTAW) __syncthreads(); else __syncwarp();
    #pragma unroll
    for (int r = 0; r < 32; ++r) S[so ^ csig(scat5(r, RMAP[GF]))] = a23[r];
    if (CTAW) __syncthreads(); else __syncwarp();
    #pragma unroll
    for (int r = 0; r < 32; ++r) a23[r] = S[sn ^ csig(scat5(r, RMAP[GT]))];
}

template<int P>
__device__ __forceinline__ void stage_body(ull* a01, ull* a23,
                                           const float4* __restrict__ Tw, int lane) {
    #pragma unroll
    for (int h = 0; h < 8; ++h) {
        float4 q = Tw[(h << 5) | lane];    // conflict-free LDS.128: rc=2h, 2h+1
        #pragma unroll
        for (int i = 0; i < 2; ++i) {
            const int rc = 2 * h + i;
            const int r0 = ((rc >> P) << (P + 1)) | (rc & ((1 << P) - 1));
            const int r1 = r0 | (1 << P);
            const float c  = i ? q.z : q.x;
            const float sv = i ? q.w : q.y;
            ull cc  = fpack(c, c);
            ull ss  = fpack(sv, sv);
            ull nss = ss ^ 0x8000000080000000ULL;
            ull A0 = a01[r0], B0 = a01[r1];
            ull A1 = a23[r0], B1 = a23[r1];
            a01[r0] = f2fma(cc, A0, f2mul(ss,  B0));
            a01[r1] = f2fma(cc, B0, f2mul(nss, A0));
            a23[r0] = f2fma(cc, A1, f2mul(ss,  B1));
            a23[r1] = f2fma(cc, B1, f2mul(nss, A1));
        }
    }
}

__global__ __launch_bounds__(128, 3)
void ob_main(const float* __restrict__ X, float* __restrict__ O) {
    extern __shared__ char smem[];
    // per-warp double-buffered coefficient slices: [buf][warp][256] float4 = 32 KB
    float4 (*wtab)[4][256] = (float4(*)[4][256])smem;
    ull* S = (ull*)(smem + 2 * 4 * 256 * sizeof(float4));   // 32 KB transpose buf

    const int tid  = threadIdx.x;        // 128 threads = one 4-row group
    const int lane = tid & 31;
    const int w    = tid >> 5;
    const long r0base = (long)blockIdx.x * 4;

    ull a01[32], a23[32];   // packed rows (0,1) and (2,3); reg idx = 5 RMAP bits

    // ---- prefetch this warp's stage-0 slice (4 KB; 8 x 16B per lane) ----
    {
        const float4* src = &g_tab4[0][w << 8];
        #pragma unroll
        for (int c = 0; c < 8; ++c) {
            int e = c * 32 + lane;
            unsigned dst = (unsigned)__cvta_generic_to_shared(&wtab[0][w][e]);
            asm volatile("cp.async.ca.shared.global [%0], [%1], 16;" :: "r"(dst), "l"(src + e));
        }
        asm volatile("cp.async.commit_group;");
    }

    // ---- coalesced load under LOAD mapping (G7): r = m + 8*component ----
    {
        const float4* s0 = (const float4*)(X + r0base * WIDTH);
        const float4* s1 = (const float4*)(X + (r0base + 1) * WIDTH);
        const float4* s2 = (const float4*)(X + (r0base + 2) * WIDTH);
        const float4* s3 = (const float4*)(X + (r0base + 3) * WIDTH);
        #pragma unroll
        for (int m = 0; m < 8; ++m) {
            int a4 = (m << 7) | (w << 5) | lane;
            float4 v0 = s0[a4], v1 = s1[a4], v2 = s2[a4], v3 = s3[a4];
            a01[m]      = fpack(v0.x, v1.x);  a23[m]      = fpack(v2.x, v3.x);
            a01[8 + m]  = fpack(v0.y, v1.y);  a23[8 + m]  = fpack(v2.y, v3.y);
            a01[16 + m] = fpack(v0.z, v1.z);  a23[16 + m] = fpack(v2.z, v3.z);
            a01[24 + m] = fpack(v0.w, v1.w);  a23[24 + m] = fpack(v2.w, v3.w);
        }
    }

    xpose<7, 0, true>(a01, a23, S, lane, w);   // LOAD -> G0 (w moves: CTA-wide)

    // ---- 32 stages; per-warp tables; R13 cp.async ordering (after xpose) ----
    #pragma unroll 1
    for (int s = 0; s < DEPTH; ++s) {
        switch (s) {           // group-boundary transposes
            case 5:  xpose<0, 1, true >(a01, a23, S, lane, w); break;  // w moves
            case 10: xpose<1, 2, true >(a01, a23, S, lane, w); break;  // w moves
            case 15: xpose<2, 3, false>(a01, a23, S, lane, w); break;  // W {10,11} fixed
            case 20: xpose<3, 4, true >(a01, a23, S, lane, w); break;  // w moves
            case 25: xpose<4, 5, true >(a01, a23, S, lane, w); break;  // w moves
            case 30: xpose<5, 6, false>(a01, a23, S, lane, w); break;  // W {10,11} fixed
            default: break;
        }
        asm volatile("cp.async.wait_group 0;");   // stage-s slice landed (per-thread:
                                                  // each lane reads only its own slots)
        if (s + 1 < DEPTH) {
            const float4* src = &g_tab4[s + 1][w << 8];
            float4* dstbuf = &wtab[(s + 1) & 1][w][0];
            #pragma unroll
            for (int c = 0; c < 8; ++c) {
                int e = c * 32 + lane;
                unsigned dst = (unsigned)__cvta_generic_to_shared(dstbuf + e);
                asm volatile("cp.async.ca.shared.global [%0], [%1], 16;" :: "r"(dst), "l"(src + e));
            }
        }
        asm volatile("cp.async.commit_group;");

        const float4* __restrict__ Tw = wtab[s & 1][w];
        switch (CP[s]) {
            case 0: stage_body<0>(a01, a23, Tw, lane); break;
            case 1: stage_body<1>(a01, a23, Tw, lane); break;
            case 2: stage_body<2>(a01, a23, Tw, lane); break;
            case 3: stage_body<3>(a01, a23, Tw, lane); break;
            default: stage_body<4>(a01, a23, Tw, lane); break;
        }
    }

    // ---- store under G6 mapping: out[j]=b32[j], float4-coalesced ----
    {
        float4* o0 = (float4*)(O + r0base * WIDTH);
        float4* o1 = (float4*)(O + (r0base + 1) * WIDTH);
        float4* o2 = (float4*)(O + (r0base + 2) * WIDTH);
        float4* o3 = (float4*)(O + (r0base + 3) * WIDTH);
        #pragma unroll
        for (int e = 0; e < 8; ++e) {
            int j4 = (w << 8) | (e << 5) | lane;
            float p0[4], p1[4], p2[4], p3[4];
            #pragma unroll
            for (int q = 0; q < 4; ++q) {
                funpack(p0[q], p1[q], a01[e * 4 + q]);
                funpack(p2[q], p3[q], a23[e * 4 + q]);
            }
            o0[j4] = make_float4(p0[0], p0[1], p0[2], p0[3]);
            o1[j4] = make_float4(p1[0], p1[1], p1[2], p1[3]);
            o2[j4] = make_float4(p2[0], p2[1], p2[2], p2[3]);
            o3[j4] = make_float4(p3[0], p3[1], p3[2], p3[3]);
        }
    }
}

extern "C" void kernel_launch(void* const* d_in, const int* in_sizes, int n_in,
                              void* d_out, int out_size) {
    const float* X = (const float*)d_in[0];
    const float* P = (const float*)d_in[1];
    if (n_in >= 2 && in_sizes[0] == DEPTH * HALFW) { const float* tmp = X; X = P; P = tmp; }
    float* O = (float*)d_out;
    const int smem = 2 * 4 * 256 * sizeof(float4) + WIDTH * sizeof(ull);  // 64 KB
    cudaFuncSetAttribute(ob_main, cudaFuncAttributeMaxDynamicSharedMemorySize, smem);
    ob_tables<<<(DEPTH * 1024 + 255) / 256, 256>>>(P);
    ob_main<<<BATCH / 4, 128, smem>>>(X, O);
}